// round 13
// baseline (speedup 1.0000x reference)
#include <cuda_runtime.h>
#include <cuda_bf16.h>
#include <cstdint>

// Stencil gather: out[b][j][k][{center,up,right,down,left}], edge-replicate.
// Input [16,1024,1024] fp32 (64 MB), output [16,1024,1024,5] (320 MB).
//
// Round-12: R11 compute path (best: 72.1us, 32 regs) with the ENTIRE store
// path moved off the SM pipeline. Every prior variant (occ 60-81%, issue
// 23-35%) pinned DRAM at ~63% because all 320 MB flowed through warp-issued
// LDS+STG. Here the transposed rows are drained by the async proxy:
// cp.async.bulk (shared::cta -> global), double-buffered per warp, so
// stores cost zero warp issue slots and zero L1 wavefronts.

#define W    1024
#define H    1024
#define NB   16
#define TPB  256
#define RPB  32                  // rows walked per block (even)
#define STRIPS (W / TPB)         // 4
#define BANDS  (H / RPB)         // 32

__global__ __launch_bounds__(TPB, 8)
void stencil5_kernel(const float* __restrict__ x, float* __restrict__ out)
{
    // Per-warp double buffer: 2 stages x 2 rows x 160 words (each row's
    // 640 B segment is contiguous = exact gmem layout for the bulk copy).
    __shared__ __align__(16) float sbuf[TPB / 32][2][320];

    const int b     = blockIdx.x;              // img*128 + band*4 + strip
    const int strip =  b        & (STRIPS - 1);
    const int band  = (b >> 2)  & (BANDS - 1);
    const int img   =  b >> 7;

    const int t    = threadIdx.x;
    const int w    = t >> 5;
    const int lane = t & 31;
    const int k    = strip * TPB + t;          // this lane's pixel column
    const int kw   = strip * TPB + (w << 5);   // warp's base column
    const int j0   = band * RPB;

    const float* xim = x + (size_t)img * (H * W);
    const float* xc  = xim + k;                // column pointer (stride W)

    // Rolling state: rm1 = row j-1 (clamped), r0 = row j.
    float rm1 = xc[(size_t)(j0 ? j0 - 1 : 0) * W];
    float r0  = xc[(size_t)j0 * W];

    float* op = out + (((size_t)img * H + j0) * W + kw) * 5;

    for (int c2 = 0; c2 < RPB / 2; ++c2) {
        const int j  = j0 + 2 * c2;
        float* buf   = sbuf[w][c2 & 1];

        // Retire the bulk group that used this stage buffer (issued c2-2).
        if (c2 >= 2) {
            if (lane == 0)
                asm volatile("cp.async.bulk.wait_group 1;" ::: "memory");
            __syncwarp();
        }

        // Two independent row loads (rows j+1, j+2); only j+2 can clamp.
        const float n1 = xc[(size_t)(j + 1) * W];
        const float n2 = xc[(size_t)(j + 2 < H ? j + 2 : H - 1) * W];

        // ---- row j:   c=r0, u=rm1, d=n1 ----
        {
            float lv = __shfl_up_sync(0xFFFFFFFFu, r0, 1);
            float rv = __shfl_down_sync(0xFFFFFFFFu, r0, 1);
            const float* row = xim + (size_t)j * W;
            if (lane == 0)  lv = (k == 0)     ? r0 : row[k - 1];  // L1 hit
            if (lane == 31) rv = (k == W - 1) ? r0 : row[k + 1];  // L1 hit
            const int s = 5 * lane;                // stride-5: conflict-free
            buf[s + 0] = r0;
            buf[s + 1] = rm1;
            buf[s + 2] = rv;
            buf[s + 3] = n1;
            buf[s + 4] = lv;
        }
        // ---- row j+1: c=n1, u=r0, d=n2 ----
        {
            float lv = __shfl_up_sync(0xFFFFFFFFu, n1, 1);
            float rv = __shfl_down_sync(0xFFFFFFFFu, n1, 1);
            const float* row = xim + (size_t)(j + 1) * W;
            if (lane == 0)  lv = (k == 0)     ? n1 : row[k - 1];
            if (lane == 31) rv = (k == W - 1) ? n1 : row[k + 1];
            const int s = 160 + 5 * lane;
            buf[s + 0] = n1;
            buf[s + 1] = r0;
            buf[s + 2] = rv;
            buf[s + 3] = n2;
            buf[s + 4] = lv;
        }

        // Order generic-proxy STS before the async-proxy bulk read, then
        // lane 0 hands both 640 B row segments to the TMA engine.
        asm volatile("fence.proxy.async.shared::cta;" ::: "memory");
        __syncwarp();
        if (lane == 0) {
            uint32_t s0 = (uint32_t)__cvta_generic_to_shared(buf);
            asm volatile(
                "cp.async.bulk.global.shared::cta.bulk_group [%0], [%1], 640;"
                :: "l"(op), "r"(s0) : "memory");
            asm volatile(
                "cp.async.bulk.global.shared::cta.bulk_group [%0], [%1], 640;"
                :: "l"(op + (size_t)W * 5), "r"(s0 + 640) : "memory");
            asm volatile("cp.async.bulk.commit_group;" ::: "memory");
        }

        // Roll.
        rm1 = n1; r0 = n2;
        op += (size_t)(W * 5) * 2;
    }

    // Drain all outstanding bulk stores before exit.
    if (lane == 0)
        asm volatile("cp.async.bulk.wait_group 0;" ::: "memory");
}

extern "C" void kernel_launch(void* const* d_in, const int* in_sizes, int n_in,
                              void* d_out, int out_size)
{
    const float* x = (const float*)d_in[0];
    float* out = (float*)d_out;
    (void)in_sizes; (void)n_in; (void)out_size;

    // 8 blocks/SM x 20.5 KB smem needs the full carveout.
    static bool configured = false;
    if (!configured) {
        cudaFuncSetAttribute(stencil5_kernel,
                             cudaFuncAttributePreferredSharedMemoryCarveout, 100);
        configured = true;
    }

    stencil5_kernel<<<NB * STRIPS * BANDS, TPB>>>(x, out);
}

// round 17
// speedup vs baseline: 1.0396x; 1.0396x over previous
#include <cuda_runtime.h>
#include <cuda_bf16.h>
#include <cstdint>

// Stencil gather: out[b][j][k][{center,up,right,down,left}], edge-replicate.
// Input [16,1024,1024] fp32 (64 MB), output [16,1024,1024,5] (320 MB).
//
// Round-13: TMA store offload at 8x the grain of round 12. R12 proved the
// async-proxy drain raises DRAM (65.6%, best) but its 524K x 640 B bulk ops
// burned the win in per-op overhead (ALU 23.5%). Here the whole block stages
// 2 rows contiguously (2 x 5120 B) and ONE thread issues 2 bulk ops + 1
// commit per chunk: 65K ops, fences/commits amortized 8x, per-warp drain
// loops gone. Compute path identical to R11/R12 (32 regs, rolling rows,
// shuffle neighbors, stride-5 conflict-free STS transpose).

#define W    1024
#define H    1024
#define NB   16
#define TPB  256
#define RPB  32                  // rows walked per block (even)
#define STRIPS (W / TPB)         // 4
#define BANDS  (H / RPB)         // 32
#define ROWSEG (TPB * 5)         // 1280 floats = 5120 B per block-row segment

__global__ __launch_bounds__(TPB, 8)
void stencil5_kernel(const float* __restrict__ x, float* __restrict__ out)
{
    // Double-buffered block stage: 2 stages x 2 rows x 1280 floats = 20.5 KB.
    __shared__ __align__(16) float sbuf[2][2 * ROWSEG];

    const int b     = blockIdx.x;              // img*128 + band*4 + strip
    const int strip =  b        & (STRIPS - 1);
    const int band  = (b >> 2)  & (BANDS - 1);
    const int img   =  b >> 7;

    const int t    = threadIdx.x;
    const int w    = t >> 5;
    const int lane = t & 31;
    const int k    = strip * TPB + t;          // this lane's pixel column
    const int j0   = band * RPB;

    const float* xim = x + (size_t)img * (H * W);
    const float* xc  = xim + k;                // column pointer (stride W)

    // Rolling state: rm1 = row j-1 (clamped), r0 = row j.
    float rm1 = xc[(size_t)(j0 ? j0 - 1 : 0) * W];
    float r0  = xc[(size_t)j0 * W];

    // Block's output segment for row j0 (5120 B, 128B-aligned).
    float* op = out + (((size_t)img * H + j0) * W + (size_t)strip * TPB) * 5;

    for (int c2 = 0; c2 < RPB / 2; ++c2) {
        const int j = j0 + 2 * c2;
        float* buf  = sbuf[c2 & 1];
        float* seg  = buf + w * 160;           // this warp's row-j slice

        // Retire the bulk group that used this stage (issued at c2-2),
        // then make the buffer free block-wide.
        if (c2 >= 2) {
            if (t == 0)
                asm volatile("cp.async.bulk.wait_group 1;" ::: "memory");
            __syncthreads();
        }

        // Two independent row loads (rows j+1, j+2); only j+2 can clamp.
        const float n1 = xc[(size_t)(j + 1) * W];
        const float n2 = xc[(size_t)(j + 2 < H ? j + 2 : H - 1) * W];

        // ---- row j:   c=r0, u=rm1, d=n1 ----
        {
            float lv = __shfl_up_sync(0xFFFFFFFFu, r0, 1);
            float rv = __shfl_down_sync(0xFFFFFFFFu, r0, 1);
            const float* row = xim + (size_t)j * W;
            if (lane == 0)  lv = (k == 0)     ? r0 : row[k - 1];  // L1 hit
            if (lane == 31) rv = (k == W - 1) ? r0 : row[k + 1];  // L1 hit
            const int s = 5 * lane;                // stride-5: conflict-free
            seg[s + 0] = r0;
            seg[s + 1] = rm1;
            seg[s + 2] = rv;
            seg[s + 3] = n1;
            seg[s + 4] = lv;
        }
        // ---- row j+1: c=n1, u=r0, d=n2 ----
        {
            float lv = __shfl_up_sync(0xFFFFFFFFu, n1, 1);
            float rv = __shfl_down_sync(0xFFFFFFFFu, n1, 1);
            const float* row = xim + (size_t)(j + 1) * W;
            if (lane == 0)  lv = (k == 0)     ? n1 : row[k - 1];
            if (lane == 31) rv = (k == W - 1) ? n1 : row[k + 1];
            const int s = ROWSEG + 5 * lane;
            seg[s + 0] = n1;
            seg[s + 1] = r0;
            seg[s + 2] = rv;
            seg[s + 3] = n2;
            seg[s + 4] = lv;
        }

        // All warps' STS visible, then one thread hands both 5120 B row
        // segments to the async proxy.
        __syncthreads();
        if (t == 0) {
            asm volatile("fence.proxy.async.shared::cta;" ::: "memory");
            uint32_t s0 = (uint32_t)__cvta_generic_to_shared(buf);
            asm volatile(
                "cp.async.bulk.global.shared::cta.bulk_group [%0], [%1], %2;"
                :: "l"(op), "r"(s0), "n"(ROWSEG * 4) : "memory");
            asm volatile(
                "cp.async.bulk.global.shared::cta.bulk_group [%0], [%1], %2;"
                :: "l"(op + (size_t)W * 5), "r"(s0 + ROWSEG * 4),
                   "n"(ROWSEG * 4) : "memory");
            asm volatile("cp.async.bulk.commit_group;" ::: "memory");
        }

        // Roll.
        rm1 = n1; r0 = n2;
        op += (size_t)(W * 5) * 2;
    }

    // Drain all outstanding bulk stores before exit.
    if (t == 0)
        asm volatile("cp.async.bulk.wait_group 0;" ::: "memory");
}

extern "C" void kernel_launch(void* const* d_in, const int* in_sizes, int n_in,
                              void* d_out, int out_size)
{
    const float* x = (const float*)d_in[0];
    float* out = (float*)d_out;
    (void)in_sizes; (void)n_in; (void)out_size;

    // 8 blocks/SM x 20.5 KB smem needs the full carveout.
    static bool configured = false;
    if (!configured) {
        cudaFuncSetAttribute(stencil5_kernel,
                             cudaFuncAttributePreferredSharedMemoryCarveout, 100);
        configured = true;
    }

    stencil5_kernel<<<NB * STRIPS * BANDS, TPB>>>(x, out);
}